// round 12
// baseline (speedup 1.0000x reference)
#include <cuda_runtime.h>
#include <cstdint>

// x: [32, 512, 56, 56] fp32, chunks of 8 batches (51.4 MB, L2-resident).
// 5 launches, excitation embedded via last-block-done counters:
//   R0         : reduce chunk0 (block/slice, 6.28 TB/s shape); last block of
//                each batch computes that batch's excitation in-place.
//   SA(c, c+1) : coalesced scale chunk c (L2 reads + DRAM writes) + fused
//                reduce-accumulate chunk c+1 (DRAM reads -> prime L2); last
//                block per (c+1)-batch computes its excitation.
// DRAM total: 410 MB vs 616 MB unchunked.

#define C            512
#define CR           32
#define SPATIAL4     784                       // f4 per slice
#define CHUNK_B      8
#define NCHUNK       4
#define CHUNK_SLICES 4096
#define CHUNK_F4     (CHUNK_SLICES * SPATIAL4) // 3,211,264
#define NBLK         3136                      // CHUNK_F4 / 1024
#define BLKS_PER_BATCH_SA 392                  // 401408 f4 / 1024
#define BLKS_PER_BATCH_R0 512                  // slices per batch

__device__ float d_sq[32 * C];                 // RAW sums (atomic-accumulated)
__device__ float d_e[32 * C];
__device__ unsigned int g_cnt[32];             // per-batch completion counters

// ---------------------------------------------------------------------------
// Excitation for one batch, run by ONE block (threads >= 128, mult of 32).
// Reads raw sums via __ldcg, scales by 1/3136, zeroes them (replay-safe).
// ---------------------------------------------------------------------------
__device__ __forceinline__ void excite_batch(
    int gb,
    const float* __restrict__ w1, const float* __restrict__ b1,
    const float* __restrict__ w2, const float* __restrict__ b2,
    float* sq, float* hid)
{
    const int tid    = threadIdx.x;
    const int nthr   = blockDim.x;
    const int nwarps = nthr >> 5;
    const int wid    = tid >> 5;
    const int lane   = tid & 31;

    for (int i = tid; i < C; i += nthr)
        sq[i] = __ldcg(&d_sq[gb * C + i]) * (1.0f / 3136.0f);
    __syncthreads();
    for (int i = tid; i < C; i += nthr)
        d_sq[gb * C + i] = 0.0f;               // reset for next replay

    for (int u = wid; u < CR; u += nwarps) {
        const float* __restrict__ wrow = w1 + (size_t)u * C;
        float acc = 0.0f;
        #pragma unroll
        for (int k = 0; k < 16; ++k) {
            const int idx = lane + 32 * k;
            acc = fmaf(sq[idx], __ldg(&wrow[idx]), acc);
        }
        #pragma unroll
        for (int off = 16; off > 0; off >>= 1)
            acc += __shfl_down_sync(0xFFFFFFFFu, acc, off);
        if (lane == 0) hid[u] = fmaxf(acc + __ldg(&b1[u]), 0.0f);
    }
    __syncthreads();

    for (int c = tid; c < C; c += nthr) {
        float acc = __ldg(&b2[c]);
        const float* __restrict__ w2r = w2 + (size_t)c * CR;
        #pragma unroll
        for (int j = 0; j < CR; ++j)
            acc = fmaf(hid[j], __ldg(&w2r[j]), acc);
        d_e[gb * C + c] = 1.0f / (1.0f + __expf(-acc));
    }
}

// ---------------------------------------------------------------------------
// R0: one block per slice of chunk 0 (proven 6.28 TB/s shape). Last block of
// each batch runs the batch's excitation.
// ---------------------------------------------------------------------------
__global__ __launch_bounds__(128) void se_reduce0(
    const float* __restrict__ x,
    const float* __restrict__ w1, const float* __restrict__ b1,
    const float* __restrict__ w2, const float* __restrict__ b2)
{
    const int s  = blockIdx.x;                  // slice in chunk 0
    const int gb = s >> 9;                      // batch 0..7
    const float4* __restrict__ p =
        reinterpret_cast<const float4*>(x) + (size_t)s * SPATIAL4;

    float acc = 0.0f;
    #pragma unroll
    for (int i = threadIdx.x; i < SPATIAL4; i += 128) {
        float4 v = p[i];
        acc += (v.x + v.y) + (v.z + v.w);
    }
    #pragma unroll
    for (int off = 16; off > 0; off >>= 1)
        acc += __shfl_down_sync(0xFFFFFFFFu, acc, off);

    __shared__ float ws[4];
    __shared__ float sq_s[C];
    __shared__ float hid_s[CR];
    __shared__ bool  is_last;

    const int lane = threadIdx.x & 31;
    if (lane == 0) ws[threadIdx.x >> 5] = acc;
    __syncthreads();

    if (threadIdx.x == 0) {
        d_sq[s] = ws[0] + ws[1] + ws[2] + ws[3];
        __threadfence();
        is_last = (atomicAdd(&g_cnt[gb], 1u) == BLKS_PER_BATCH_R0 - 1u);
    }
    __syncthreads();

    if (is_last) {
        excite_batch(gb, w1, b1, w2, b2, sq_s, hid_s);
        __syncthreads();
        if (threadIdx.x == 0) atomicExch(&g_cnt[gb], 0u);
    }
}

// ---------------------------------------------------------------------------
// SA: coalesced (stride-256 interleave) scale of chunk sc + fused
// reduce-accumulate of chunk rc. Each block owns a contiguous 1024-f4 span;
// 392 blocks per batch. Last block per rc-batch runs its excitation.
// ---------------------------------------------------------------------------
__global__ __launch_bounds__(256) void se_scale_accum(
    const float* __restrict__ x,
    float* __restrict__ out,
    const float* __restrict__ w1, const float* __restrict__ b1,
    const float* __restrict__ w2, const float* __restrict__ b2,
    int sc, int rc)
{
    const unsigned int i0 = blockIdx.x * 1024u + threadIdx.x;
    const int lane = threadIdx.x & 31;

    const float4* __restrict__ x4 = reinterpret_cast<const float4*>(x);
    float4*       __restrict__ o4 = reinterpret_cast<float4*>(out);

    const unsigned int base_s = (unsigned int)sc * CHUNK_F4 + i0;

    // batched coalesced loads: 4 scale f4 (+4 reduce f4) in flight
    float4 vs[4];
    #pragma unroll
    for (int j = 0; j < 4; ++j)
        vs[j] = __ldcs(x4 + base_s + j * 256u);

    float sred[4];
    unsigned int base_r = 0;
    if (rc >= 0) {
        base_r = (unsigned int)rc * CHUNK_F4 + i0;
        #pragma unroll
        for (int j = 0; j < 4; ++j) {
            const float4 v = x4[base_r + j * 256u];   // default: keep in L2
            sred[j] = (v.x + v.y) + (v.z + v.w);
        }
    }

    // scale + store (coalesced)
    #pragma unroll
    for (int j = 0; j < 4; ++j) {
        const float e = __ldg(&d_e[(base_s + j * 256u) / 784u]);
        float4 r = vs[j];
        r.x *= e; r.y *= e; r.z *= e; r.w *= e;
        __stcs(o4 + base_s + j * 256u, r);
    }

    if (rc >= 0) {
        // per-j head-segmented warp reduction keyed by global slice id
        #pragma unroll
        for (int j = 0; j < 4; ++j) {
            float s  = sred[j];
            int  key = (int)((base_r + j * 256u) / 784u);
            #pragma unroll
            for (int off = 16; off > 0; off >>= 1) {
                const float v2 = __shfl_down_sync(0xFFFFFFFFu, s, off);
                const int   k2 = __shfl_down_sync(0xFFFFFFFFu, key, off);
                if (lane + off < 32 && k2 == key) s += v2;
            }
            const int keyprev = __shfl_up_sync(0xFFFFFFFFu, key, 1);
            if (lane == 0 || keyprev != key)
                atomicAdd(&d_sq[key], s);
        }

        // ---- last-block-per-batch -> excitation ----
        __shared__ bool  is_last;
        __shared__ float sq_s[C];
        __shared__ float hid_s[CR];
        const int lb = blockIdx.x / BLKS_PER_BATCH_SA;   // 0..7
        const int gb = rc * CHUNK_B + lb;
        __syncthreads();
        if (threadIdx.x == 0) {
            __threadfence();
            is_last = (atomicAdd(&g_cnt[gb], 1u) == BLKS_PER_BATCH_SA - 1u);
        }
        __syncthreads();
        if (is_last) {
            excite_batch(gb, w1, b1, w2, b2, sq_s, hid_s);
            __syncthreads();
            if (threadIdx.x == 0) atomicExch(&g_cnt[gb], 0u);
        }
    }
}

// ---------------------------------------------------------------------------
extern "C" void kernel_launch(void* const* d_in, const int* in_sizes, int n_in,
                              void* d_out, int out_size) {
    const float* x  = (const float*)d_in[0];
    const float* w1 = (const float*)d_in[1];
    const float* b1 = (const float*)d_in[2];
    const float* w2 = (const float*)d_in[3];
    const float* b2 = (const float*)d_in[4];
    float* out = (float*)d_out;

    se_reduce0<<<CHUNK_SLICES, 128>>>(x, w1, b1, w2, b2);
    for (int c = 0; c < NCHUNK; ++c) {
        const int rc = (c + 1 < NCHUNK) ? c + 1 : -1;
        se_scale_accum<<<NBLK, 256>>>(x, out, w1, b1, w2, b2, c, rc);
    }
}

// round 13
// speedup vs baseline: 1.0860x; 1.0860x over previous
#include <cuda_runtime.h>
#include <cstdint>

// x: [32, 512, 56, 56] fp32, chunks of 8 batches (51.4 MB, L2-resident).
// 5 launches:
//   R0         : reduce chunk0 (block/slice, 6.28 TB/s shape); zero chunks
//                1-3 raw sums; last block per batch -> FC1 (warp0) -> d_hid.
//   SA(c, c+1) : prologue: threads 0..2 compute e for the block's <=3 slices
//                from d_hid (FC2+sigmoid), one __syncthreads BEFORE streaming.
//                Streaming: coalesced scale chunk c (L2 reads + DRAM writes)
//                + fused reduce-accumulate chunk c+1 (DRAM reads, primes L2).
//                Tail: warp-granularity counter; last warp per (c+1)-batch
//                computes FC1 -> d_hid. NO block barriers after streaming.
// DRAM total: 410 MB vs 616 MB unchunked.

#define C            512
#define CR           32
#define SPATIAL4     784                       // f4 per slice
#define CHUNK_B      8
#define NCHUNK       4
#define CHUNK_SLICES 4096
#define CHUNK_F4     (CHUNK_SLICES * SPATIAL4) // 3,211,264
#define NBLK         3136                      // CHUNK_F4 / 1024
#define BLKS_PER_BATCH_SA  392                 // 401408 f4 / 1024
#define WARPS_PER_BATCH_SA 3136                // 392 * 8
#define BLKS_PER_BATCH_R0  512

__device__ float d_sq[32 * C];                 // RAW sums
__device__ float d_hid[32 * CR];               // per-batch hidden units
__device__ unsigned int g_cnt[32];             // completion counters (0-init)

// ---------------------------------------------------------------------------
// FC1 for one batch, executed by ONE warp. lane l -> hid[l].
// Reads raw sums via __ldcg (atomics live in L2), applies 1/3136 at the end.
// ---------------------------------------------------------------------------
__device__ __forceinline__ void fc1_warp(
    int gb, int lane,
    const float* __restrict__ w1, const float* __restrict__ b1)
{
    const float4* __restrict__ sv =
        reinterpret_cast<const float4*>(d_sq + (size_t)gb * C);
    const float4* __restrict__ wv =
        reinterpret_cast<const float4*>(w1 + (size_t)lane * C);
    float a0 = 0.f, a1 = 0.f, a2 = 0.f, a3 = 0.f;
    #pragma unroll 8
    for (int i = 0; i < C / 4; ++i) {
        const float4 s = __ldcg(&sv[i]);
        const float4 w = __ldg(&wv[i]);
        a0 = fmaf(s.x, w.x, a0);
        a1 = fmaf(s.y, w.y, a1);
        a2 = fmaf(s.z, w.z, a2);
        a3 = fmaf(s.w, w.w, a3);
    }
    const float dot = (a0 + a1) + (a2 + a3);
    d_hid[gb * CR + lane] =
        fmaxf(dot * (1.0f / 3136.0f) + __ldg(&b1[lane]), 0.0f);
}

// ---------------------------------------------------------------------------
// R0: one block per slice of chunk 0. Blocks 0..95 also zero chunks 1-3 raw
// sums. Last block of each batch: warp0 computes FC1 -> d_hid.
// ---------------------------------------------------------------------------
__global__ __launch_bounds__(128) void se_reduce0(
    const float* __restrict__ x,
    const float* __restrict__ w1, const float* __restrict__ b1)
{
    const int s  = blockIdx.x;                  // slice in chunk 0
    const int gb = s >> 9;                      // batch 0..7

    // zero chunks 1..3 raw sums: 12288 floats over blocks 0..95
    if (blockIdx.x < 96)
        d_sq[CHUNK_SLICES + blockIdx.x * 128 + threadIdx.x] = 0.0f;

    const float4* __restrict__ p =
        reinterpret_cast<const float4*>(x) + (size_t)s * SPATIAL4;

    float acc = 0.0f;
    #pragma unroll
    for (int i = threadIdx.x; i < SPATIAL4; i += 128) {
        float4 v = p[i];
        acc += (v.x + v.y) + (v.z + v.w);
    }
    #pragma unroll
    for (int off = 16; off > 0; off >>= 1)
        acc += __shfl_down_sync(0xFFFFFFFFu, acc, off);

    __shared__ float ws[4];
    __shared__ int   last_s;
    const int lane = threadIdx.x & 31;
    if (lane == 0) ws[threadIdx.x >> 5] = acc;
    __syncthreads();

    if (threadIdx.x == 0) {
        d_sq[s] = ws[0] + ws[1] + ws[2] + ws[3];
        __threadfence();
        last_s = (atomicAdd(&g_cnt[gb], 1u) == BLKS_PER_BATCH_R0 - 1u);
    }
    __syncthreads();

    if (last_s && threadIdx.x < 32) {           // warp0 only
        __threadfence();                        // acquire
        fc1_warp(gb, lane, w1, b1);
        __syncwarp();
        if (lane == 0) atomicExch(&g_cnt[gb], 0u);
    }
}

// ---------------------------------------------------------------------------
// SA: prologue (e for <=3 slices) + coalesced streaming + warp-counter tail.
// ---------------------------------------------------------------------------
__global__ __launch_bounds__(256) void se_scale_accum(
    const float* __restrict__ x,
    float* __restrict__ out,
    const float* __restrict__ w1, const float* __restrict__ b1,
    const float* __restrict__ w2, const float* __restrict__ b2,
    int sc, int rc)
{
    const int tid  = threadIdx.x;
    const int lane = tid & 31;

    const unsigned int i0 = blockIdx.x * 1024u + tid;   // chunk-relative f4
    const float4* __restrict__ x4 = reinterpret_cast<const float4*>(x);
    float4*       __restrict__ o4 = reinterpret_cast<float4*>(out);

    const unsigned int base_s = (unsigned int)sc * CHUNK_F4 + i0;

    // ---- issue all big loads first (MLP=8 during prologue) ----
    float4 vs[4];
    #pragma unroll
    for (int j = 0; j < 4; ++j)
        vs[j] = __ldcs(x4 + base_s + j * 256u);

    float4 vr[4];
    unsigned int base_r = 0;
    if (rc >= 0) {
        base_r = (unsigned int)rc * CHUNK_F4 + i0;
        #pragma unroll
        for (int j = 0; j < 4; ++j)
            vr[j] = x4[base_r + j * 256u];              // default: keep in L2
    }

    // ---- prologue: e for this block's <=3 slices (FC2 + sigmoid) ----
    __shared__ float e_s[3];
    const int batch    = blockIdx.x / BLKS_PER_BATCH_SA;   // 0..7
    const unsigned int i0b = blockIdx.x * 1024u;
    const int slice_lo = (int)(i0b / 784u);
    const int nsl      = (int)((i0b + 1023u) / 784u) - slice_lo + 1;

    if (tid < nsl) {
        const int sl = slice_lo + tid;                  // chunk-relative slice
        const int ch = sl & (C - 1);
        const int gb = sc * CHUNK_B + batch;
        float acc = __ldg(&b2[ch]);
        const float* __restrict__ hp = d_hid + gb * CR;
        const float* __restrict__ wp = w2 + (size_t)ch * CR;
        #pragma unroll
        for (int j = 0; j < CR; ++j)
            acc = fmaf(hp[j], __ldg(&wp[j]), acc);
        e_s[tid] = 1.0f / (1.0f + __expf(-acc));
    }
    __syncthreads();                                    // only block barrier

    // ---- streaming: scale + store (coalesced) ----
    #pragma unroll
    for (int j = 0; j < 4; ++j) {
        const float e = e_s[(i0 + j * 256u) / 784u - slice_lo];
        float4 r = vs[j];
        r.x *= e; r.y *= e; r.z *= e; r.w *= e;
        __stcs(o4 + base_s + j * 256u, r);
    }

    if (rc >= 0) {
        // reduce-accumulate: per-j head-segmented warp reduction
        #pragma unroll
        for (int j = 0; j < 4; ++j) {
            float s = (vr[j].x + vr[j].y) + (vr[j].z + vr[j].w);
            int key = (int)((i0 + j * 256u) / 784u);    // chunk-relative slice
            #pragma unroll
            for (int off = 16; off > 0; off >>= 1) {
                const float v2 = __shfl_down_sync(0xFFFFFFFFu, s, off);
                const int   k2 = __shfl_down_sync(0xFFFFFFFFu, key, off);
                if (lane + off < 32 && k2 == key) s += v2;
            }
            const int keyprev = __shfl_up_sync(0xFFFFFFFFu, key, 1);
            if (lane == 0 || keyprev != key)
                atomicAdd(&d_sq[rc * CHUNK_SLICES + key], s);
        }

        // ---- warp-granularity tail: last warp per batch does FC1 ----
        const int gb2 = rc * CHUNK_B + batch;
        __threadfence();                                // release own atomics
        __syncwarp();
        unsigned int is_last = 0;
        if (lane == 0)
            is_last = (atomicAdd(&g_cnt[gb2], 1u) == WARPS_PER_BATCH_SA - 1u);
        is_last = __shfl_sync(0xFFFFFFFFu, is_last, 0);
        if (is_last) {
            __threadfence();                            // acquire
            fc1_warp(gb2, lane, w1, b1);
            __syncwarp();
            if (lane == 0) atomicExch(&g_cnt[gb2], 0u);
        }
    }
}

// ---------------------------------------------------------------------------
extern "C" void kernel_launch(void* const* d_in, const int* in_sizes, int n_in,
                              void* d_out, int out_size) {
    const float* x  = (const float*)d_in[0];
    const float* w1 = (const float*)d_in[1];
    const float* b1 = (const float*)d_in[2];
    const float* w2 = (const float*)d_in[3];
    const float* b2 = (const float*)d_in[4];
    float* out = (float*)d_out;

    se_reduce0<<<CHUNK_SLICES, 128>>>(x, w1, b1);
    for (int c = 0; c < NCHUNK; ++c) {
        const int rc = (c + 1 < NCHUNK) ? c + 1 : -1;
        se_scale_accum<<<NBLK, 256>>>(x, out, w1, b1, w2, b2, c, rc);
    }
}

// round 14
// speedup vs baseline: 1.6449x; 1.5147x over previous
#include <cuda_runtime.h>
#include <cstdint>

// x: [32, 512, 56, 56] fp32, chunks of 8 batches (51.4 MB, L2-resident).
// 8 launches: per chunk, (reduce + embedded excitation tail) then scale.
//   RX(c): block per slice (proven 6.28 TB/s shape). Last block of each batch
//          computes FC1+FC2+sigmoid -> d_e (one block, ~2us straggler).
//   S(c) : proven scale shape (4xf4/thread stride-256, __ldcs/__stcs);
//          chunk reads hit L2 (left there by RX), writes go to DRAM.
// DRAM total: 410 MB vs 616 MB unchunked.

#define C            512
#define CR           32
#define SPATIAL4     784                        // f4 per slice
#define CHUNK_B      8
#define NCHUNK       4
#define CHUNK_SLICES 4096
#define CHUNK_F4     (CHUNK_SLICES * SPATIAL4)  // 3,211,264
#define NSCALE       3136                       // CHUNK_F4 / 1024
#define BLKS_PER_BATCH 512                      // slices per batch

__device__ float d_sq[32 * C];                  // raw per-slice sums
__device__ float d_e[32 * C];
__device__ unsigned int g_cnt[32];              // per-batch counters (0-init)

// ---------------------------------------------------------------------------
// RX: one block per slice (128 threads). Plain store of the slice sum, then
// per-batch counter; the 512th block of a batch runs the excitation tail.
// ---------------------------------------------------------------------------
__global__ __launch_bounds__(128) void se_reduce_excite(
    const float* __restrict__ x,
    const float* __restrict__ w1, const float* __restrict__ b1,
    const float* __restrict__ w2, const float* __restrict__ b2,
    int slice0)
{
    const int s  = slice0 + blockIdx.x;         // global slice id
    const int gb = s >> 9;                      // global batch id
    const int tid  = threadIdx.x;
    const int lane = tid & 31;
    const int wid  = tid >> 5;                  // 4 warps

    const float4* __restrict__ p =
        reinterpret_cast<const float4*>(x) + (size_t)s * SPATIAL4;

    float acc = 0.0f;
    #pragma unroll
    for (int i = tid; i < SPATIAL4; i += 128) {
        float4 v = p[i];
        acc += (v.x + v.y) + (v.z + v.w);
    }
    #pragma unroll
    for (int off = 16; off > 0; off >>= 1)
        acc += __shfl_down_sync(0xFFFFFFFFu, acc, off);

    __shared__ float ws[4];
    __shared__ int   last_s;
    if (lane == 0) ws[wid] = acc;
    __syncthreads();

    if (tid == 0) {
        d_sq[s] = ws[0] + ws[1] + ws[2] + ws[3];
        __threadfence();
        last_s = (atomicAdd(&g_cnt[gb], 1u) == BLKS_PER_BATCH - 1u);
    }
    __syncthreads();

    if (!last_s) return;

    // ======================= excitation tail (one block) ====================
    __threadfence();                            // acquire: see all d_sq writes

    __shared__ float sq[C];
    __shared__ float hid[CR];

    for (int i = tid; i < C; i += 128)
        sq[i] = __ldcg(&d_sq[gb * C + i]) * (1.0f / 3136.0f);
    __syncthreads();

    // FC1: warp w -> hidden units 8w..8w+7 (lane-parallel dot + shuffle)
    #pragma unroll
    for (int r = 0; r < 8; ++r) {
        const int u = wid * 8 + r;
        const float* __restrict__ wrow = w1 + (size_t)u * C;
        float a = 0.0f;
        #pragma unroll
        for (int k = 0; k < 16; ++k) {
            const int idx = lane + 32 * k;
            a = fmaf(sq[idx], __ldg(&wrow[idx]), a);
        }
        #pragma unroll
        for (int off = 16; off > 0; off >>= 1)
            a += __shfl_down_sync(0xFFFFFFFFu, a, off);
        if (lane == 0) hid[u] = fmaxf(a + __ldg(&b1[u]), 0.0f);
    }
    __syncthreads();

    // FC2 + sigmoid: 128 threads x 4 channels (coalesced channel stride)
    #pragma unroll
    for (int i = 0; i < 4; ++i) {
        const int c = tid + 128 * i;
        float a = __ldg(&b2[c]);
        const float4* __restrict__ w2v =
            reinterpret_cast<const float4*>(w2 + (size_t)c * CR);
        #pragma unroll
        for (int j = 0; j < CR / 4; ++j) {
            const float4 w = __ldg(&w2v[j]);
            a = fmaf(hid[4 * j + 0], w.x, a);
            a = fmaf(hid[4 * j + 1], w.y, a);
            a = fmaf(hid[4 * j + 2], w.z, a);
            a = fmaf(hid[4 * j + 3], w.w, a);
        }
        d_e[gb * C + c] = 1.0f / (1.0f + __expf(-a));
    }

    __syncthreads();
    if (tid == 0) atomicExch(&g_cnt[gb], 0u);   // replay-safe reset
}

// ---------------------------------------------------------------------------
// S: proven scale shape (R5: 8.3us/chunk). 4 float4/thread, stride-256
// interleave, batched loads; __ldcs x reads (L2 hits), __stcs out writes.
// ---------------------------------------------------------------------------
__global__ __launch_bounds__(256) void se_scale_chunk(
    const float* __restrict__ x,
    float* __restrict__ out,
    unsigned int base_f4)
{
    const unsigned int i = base_f4 + blockIdx.x * 1024u + threadIdx.x;

    const float4* __restrict__ x4 = reinterpret_cast<const float4*>(x);
    float4* __restrict__ o4       = reinterpret_cast<float4*>(out);

    float4 v[4];
    float  e[4];

    #pragma unroll
    for (int j = 0; j < 4; ++j)
        v[j] = __ldcs(x4 + (i + j * 256u));

    #pragma unroll
    for (int j = 0; j < 4; ++j)
        e[j] = __ldg(&d_e[(i + j * 256u) / 784u]);

    #pragma unroll
    for (int j = 0; j < 4; ++j) {
        float4 r = v[j];
        const float s = e[j];
        r.x *= s; r.y *= s; r.z *= s; r.w *= s;
        __stcs(o4 + (i + j * 256u), r);
    }
}

// ---------------------------------------------------------------------------
extern "C" void kernel_launch(void* const* d_in, const int* in_sizes, int n_in,
                              void* d_out, int out_size) {
    const float* x  = (const float*)d_in[0];
    const float* w1 = (const float*)d_in[1];
    const float* b1 = (const float*)d_in[2];
    const float* w2 = (const float*)d_in[3];
    const float* b2 = (const float*)d_in[4];
    float* out = (float*)d_out;

    for (int c = 0; c < NCHUNK; ++c) {
        se_reduce_excite<<<CHUNK_SLICES, 128>>>(x, w1, b1, w2, b2,
                                                c * CHUNK_SLICES);
        se_scale_chunk<<<NSCALE, 256>>>(x, out,
                                        (unsigned int)c * (unsigned int)CHUNK_F4);
    }
}